// round 16
// baseline (speedup 1.0000x reference)
#include <cuda_runtime.h>
#include <cuda_bf16.h>
#include <mma.h>
#include <type_traits>
#include <cstdint>

using namespace nvcuda;

#define MT_TOK 16384
#define DMODEL 1024
#define SEQ    2048
#define NBATCH 8

// ---------------------------------------------------------------------------
// Scratch (device globals; allocation-free rule)
// ---------------------------------------------------------------------------
__device__ __nv_bfloat16 g_qb [MT_TOK * DMODEL];
__device__ __nv_bfloat16 g_kb [MT_TOK * DMODEL];
__device__ __nv_bfloat16 g_vb [MT_TOK * DMODEL];
__device__ __nv_bfloat16 g_Wqb[DMODEL * DMODEL];
__device__ __nv_bfloat16 g_Wkb[DMODEL * DMODEL];
__device__ __nv_bfloat16 g_Wvb[DMODEL * DMODEL];
__device__ __nv_bfloat16 g_Wob[DMODEL * DMODEL];
__device__ __nv_bfloat16 g_qh [MT_TOK * DMODEL];   // q-proj out (pre-scaled)
__device__ __nv_bfloat16 g_kh [MT_TOK * DMODEL];   // k-proj out (+bk)
__device__ __nv_bfloat16 g_vh [MT_TOK * DMODEL];   // v-proj out (+bv)
__device__ __nv_bfloat16 g_attn[MT_TOK * DMODEL];  // P@V out
__device__ float         g_scores[(size_t)NBATCH * SEQ * SEQ]; // fp32 scores; bf16 probs in place
__device__ float         g_attnout[MT_TOK * DMODEL];

__device__ __forceinline__ uint32_t pack_bf2(float a, float b)
{
    __nv_bfloat162 h = __floats2bfloat162_rn(a, b);
    return *reinterpret_cast<uint32_t*>(&h);
}

// ---------------------------------------------------------------------------
// cp.async helpers
// ---------------------------------------------------------------------------
__device__ __forceinline__ void cp_async16(void* smem_ptr, const void* gmem_ptr)
{
    unsigned s = (unsigned)__cvta_generic_to_shared(smem_ptr);
    asm volatile("cp.async.cg.shared.global [%0], [%1], 16;\n" :: "r"(s), "l"(gmem_ptr));
}
__device__ __forceinline__ void cp_commit()
{
    asm volatile("cp.async.commit_group;\n" ::: "memory");
}
template <int N>
__device__ __forceinline__ void cp_wait()
{
    asm volatile("cp.async.wait_group %0;\n" :: "n"(N) : "memory");
}

// ---------------------------------------------------------------------------
// Shared GEMM core (bf16 m16n16k16, fp32 accum), 3-stage cp.async pipeline.
// Block tile 128x128x32, 8 warps (warp 64x32). One __syncthreads per k-tile.
// Mainloop reordered for LDSM/HMMA overlap:
//   [LDSM fb(kk0),fb(kk16),fa(kk0)] -> [issue cp.async stream] ->
//   [mma kk0] -> [LDSM fa(kk16)] -> [mma kk16]
// ---------------------------------------------------------------------------
template <int BT, typename OutT>
__device__ __forceinline__ void gemm_core(
    const __nv_bfloat16* __restrict__ A, const __nv_bfloat16* __restrict__ Bm,
    OutT* __restrict__ C, int N, int K, int lda, int ldb,
    const float* __restrict__ bias, float scale,
    int tm, int tn, __nv_bfloat16* smem)
{
    constexpr int LDA   = 40;
    constexpr int LDB   = BT ? 40 : 136;
    constexpr int ASTG  = 128 * LDA;
    constexpr int BSTG  = BT ? (128 * LDB) : (32 * LDB);
    constexpr int STG   = ASTG + BSTG;

    const int tid  = threadIdx.x;
    const int warp = tid >> 5;
    const int lane = tid & 31;
    const int wm   = warp & 1;
    const int wn   = warp >> 1;

    const int ar  = tid >> 2;
    const int ac8 = (tid & 3) * 8;
    const int br  = BT ? ar : (tid >> 4);
    const int bc8 = BT ? ac8 : ((tid & 15) * 8);

    const __nv_bfloat16* Aor = A + (size_t)(tm + ar) * lda + ac8;
    const __nv_bfloat16* Bor = BT ? (Bm + (size_t)(tn + br) * ldb + bc8)
                                  : (Bm + (size_t)br * ldb + tn + bc8);

    auto load_stage = [&](int kt, int buf) {
        const int k0 = kt << 5;
        __nv_bfloat16* as = smem + buf * STG;
        __nv_bfloat16* bs = as + ASTG;
#pragma unroll
        for (int it = 0; it < 2; it++)
            cp_async16(&as[(ar + it * 64) * LDA + ac8],
                       Aor + (size_t)(it * 64) * lda + k0);
        if (BT) {
#pragma unroll
            for (int it = 0; it < 2; it++)
                cp_async16(&bs[(br + it * 64) * LDB + bc8],
                           Bor + (size_t)(it * 64) * ldb + k0);
        } else {
#pragma unroll
            for (int it = 0; it < 2; it++)
                cp_async16(&bs[(br + it * 16) * LDB + bc8],
                           Bor + (size_t)(k0 + it * 16) * ldb);
        }
        cp_commit();
    };

    using BLayout = typename std::conditional<(BT != 0), wmma::col_major, wmma::row_major>::type;

    wmma::fragment<wmma::accumulator, 16, 16, 16, float> fc[4][2];
#pragma unroll
    for (int i = 0; i < 4; i++)
#pragma unroll
        for (int j = 0; j < 2; j++) wmma::fill_fragment(fc[i][j], 0.0f);

    const int nk = K >> 5;
    load_stage(0, 0);
    load_stage(1, 1);

    int buf = 0;
    for (int kt = 0; kt < nk; kt++) {
        if (kt + 1 < nk) cp_wait<1>(); else cp_wait<0>();
        __syncthreads();

        const __nv_bfloat16* as = smem + buf * STG;
        const __nv_bfloat16* bs = as + ASTG;

        // --- fragment loads first: both kk-steps' B frags + kk0 A frags ---
        wmma::fragment<wmma::matrix_b, 16, 16, 16, __nv_bfloat16, BLayout> fb0[2], fb1[2];
        wmma::fragment<wmma::matrix_a, 16, 16, 16, __nv_bfloat16, wmma::row_major> fa[4];
#pragma unroll
        for (int j = 0; j < 2; j++) {
            if (BT) {
                wmma::load_matrix_sync(fb0[j], &bs[(wn * 32 + j * 16) * LDB + 0],  LDB);
                wmma::load_matrix_sync(fb1[j], &bs[(wn * 32 + j * 16) * LDB + 16], LDB);
            } else {
                wmma::load_matrix_sync(fb0[j], &bs[0  * LDB + wn * 32 + j * 16], LDB);
                wmma::load_matrix_sync(fb1[j], &bs[16 * LDB + wn * 32 + j * 16], LDB);
            }
        }
#pragma unroll
        for (int i = 0; i < 4; i++)
            wmma::load_matrix_sync(fa[i], &as[(wm * 64 + i * 16) * LDA + 0], LDA);

        // --- cp.async stream for tile kt+2 issues now (STS overlaps mma) ---
        if (kt + 2 < nk) load_stage(kt + 2, (buf + 2) % 3);

        // --- mma kk=0 ---
#pragma unroll
        for (int i = 0; i < 4; i++)
#pragma unroll
            for (int j = 0; j < 2; j++)
                wmma::mma_sync(fc[i][j], fa[i], fb0[j], fc[i][j]);

        // --- reload A frags for kk=16 (overlaps tail of kk0 mma chain) ---
#pragma unroll
        for (int i = 0; i < 4; i++)
            wmma::load_matrix_sync(fa[i], &as[(wm * 64 + i * 16) * LDA + 16], LDA);

        // --- mma kk=16 ---
#pragma unroll
        for (int i = 0; i < 4; i++)
#pragma unroll
            for (int j = 0; j < 2; j++)
                wmma::mma_sync(fc[i][j], fa[i], fb1[j], fc[i][j]);

        buf = (buf + 1) % 3;
    }
    __syncthreads();   // smem dead; reusable for epilogue bounce

    constexpr bool OUT_F32 = std::is_same<OutT, float>::value;
    if (OUT_F32 && bias == nullptr) {
#pragma unroll
        for (int i = 0; i < 4; i++)
#pragma unroll
            for (int j = 0; j < 2; j++) {
#pragma unroll
                for (int t = 0; t < fc[i][j].num_elements; t++) fc[i][j].x[t] *= scale;
                int gr = tm + wm * 64 + i * 16;
                int gc = tn + wn * 32 + j * 16;
                wmma::store_matrix_sync((float*)C + (size_t)gr * N + gc, fc[i][j], N,
                                        wmma::mem_row_major);
            }
    } else {
        float* ct = reinterpret_cast<float*>(smem) + warp * 256;
#pragma unroll
        for (int i = 0; i < 4; i++) {
#pragma unroll
            for (int j = 0; j < 2; j++) {
#pragma unroll
                for (int t = 0; t < fc[i][j].num_elements; t++) fc[i][j].x[t] *= scale;
                wmma::store_matrix_sync(ct, fc[i][j], 16, wmma::mem_row_major);
                __syncwarp();
                int r  = lane >> 1;
                int cb = (lane & 1) * 8;
                int gr = tm + wm * 64 + i * 16 + r;
                int gc = tn + wn * 32 + j * 16 + cb;
                float v[8];
#pragma unroll
                for (int e = 0; e < 8; e++) {
                    v[e] = ct[r * 16 + cb + e];
                    if (bias) v[e] += __ldg(&bias[gc + e]);
                }
                if (OUT_F32) {
                    float* cp = (float*)C + (size_t)gr * N + gc;
                    *reinterpret_cast<float4*>(cp)     = make_float4(v[0], v[1], v[2], v[3]);
                    *reinterpret_cast<float4*>(cp + 4) = make_float4(v[4], v[5], v[6], v[7]);
                } else {
                    __nv_bfloat16* cp = (__nv_bfloat16*)C + (size_t)gr * N + gc;
                    uint4 u;
                    u.x = pack_bf2(v[0], v[1]); u.y = pack_bf2(v[2], v[3]);
                    u.z = pack_bf2(v[4], v[5]); u.w = pack_bf2(v[6], v[7]);
                    *reinterpret_cast<uint4*>(cp) = u;
                }
                __syncwarp();
            }
        }
    }
}

// ---------------------------------------------------------------------------
// Generic batched GEMM wrapper (z = batch)
// ---------------------------------------------------------------------------
template <int BT, typename OutT>
__global__ void __launch_bounds__(256, 2) gemm_bf16(
    const __nv_bfloat16* __restrict__ A, const __nv_bfloat16* __restrict__ Bm,
    OutT* __restrict__ C, int M, int N, int K, int lda, int ldb,
    long long sA, long long sB, long long sC,
    const float* __restrict__ bias, float scale)
{
    extern __shared__ __align__(16) __nv_bfloat16 smem[];
    const long long bz = blockIdx.z;
    gemm_core<BT, OutT>(A + bz * sA, Bm + bz * sB, C + bz * sC,
                        N, K, lda, ldb, bias, scale,
                        blockIdx.y * 128, blockIdx.x * 128, smem);
}

// ---------------------------------------------------------------------------
// Fused QKV projection: one launch, z in {0,1,2} selects (A, W, C, bias, scale)
// ---------------------------------------------------------------------------
struct QKVArgs {
    const __nv_bfloat16* A[3];
    const __nv_bfloat16* B[3];
    __nv_bfloat16*       C[3];
    const float*         bias[3];
    float                scale[3];
};

__global__ void __launch_bounds__(256, 2) gemm_qkv(QKVArgs args)
{
    extern __shared__ __align__(16) __nv_bfloat16 smem[];
    const int z = blockIdx.z;
    gemm_core<1, __nv_bfloat16>(args.A[z], args.B[z], args.C[z],
                                DMODEL, DMODEL, DMODEL, DMODEL,
                                args.bias[z], args.scale[z],
                                blockIdx.y * 128, blockIdx.x * 128, smem);
}

// smem sizes (bytes)
#define SMEM_NT (3 * (128 * 40 + 128 * 40) * 2)
#define SMEM_NN (3 * (128 * 40 + 32 * 136) * 2)

// ---------------------------------------------------------------------------
// Fused fp32 -> bf16 conversions (z-indexed tensor arrays)
// ---------------------------------------------------------------------------
struct CvtArgs {
    const float*   in[4];
    __nv_bfloat16* out[4];
};

__global__ void __launch_bounds__(256) f2bf_multi(CvtArgs args, int n)
{
    const int z = blockIdx.z;
    const float* in = args.in[z];
    __nv_bfloat16* out = args.out[z];
    int i = (blockIdx.x * 256 + threadIdx.x) * 8;
    if (i >= n) return;
    float4 a = *reinterpret_cast<const float4*>(in + i);
    float4 b = *reinterpret_cast<const float4*>(in + i + 4);
    uint4 u;
    u.x = pack_bf2(a.x, a.y); u.y = pack_bf2(a.z, a.w);
    u.z = pack_bf2(b.x, b.y); u.w = pack_bf2(b.z, b.w);
    *reinterpret_cast<uint4*>(out + i) = u;
}

// ---------------------------------------------------------------------------
// reductions
// ---------------------------------------------------------------------------
__device__ __forceinline__ float block_reduce_max(float v, float* sred)
{
    int lane = threadIdx.x & 31, warp = threadIdx.x >> 5;
#pragma unroll
    for (int o = 16; o > 0; o >>= 1) v = fmaxf(v, __shfl_xor_sync(0xffffffffu, v, o));
    if (lane == 0) sred[warp] = v;
    __syncthreads();
    if (warp == 0) {
        v = (lane < 8) ? sred[lane] : -3.402823e38f;
#pragma unroll
        for (int o = 4; o > 0; o >>= 1) v = fmaxf(v, __shfl_xor_sync(0xffffffffu, v, o));
        if (lane == 0) sred[0] = v;
    }
    __syncthreads();
    return sred[0];
}
__device__ __forceinline__ float block_reduce_sum(float v, float* sred)
{
    int lane = threadIdx.x & 31, warp = threadIdx.x >> 5;
#pragma unroll
    for (int o = 16; o > 0; o >>= 1) v += __shfl_xor_sync(0xffffffffu, v, o);
    if (lane == 0) sred[warp] = v;
    __syncthreads();
    if (warp == 0) {
        v = (lane < 8) ? sred[lane] : 0.0f;
#pragma unroll
        for (int o = 4; o > 0; o >>= 1) v += __shfl_xor_sync(0xffffffffu, v, o);
        if (lane == 0) sred[0] = v;
    }
    __syncthreads();
    return sred[0];
}

// ---------------------------------------------------------------------------
// Softmax over 2048 fp32 -> bf16 probs in place (row stride preserved)
// ---------------------------------------------------------------------------
__global__ void __launch_bounds__(256) softmax_kernel(float* __restrict__ P)
{
    __shared__ float sred[32];
    size_t row = blockIdx.x;
    float4* p = reinterpret_cast<float4*>(P + row * (size_t)SEQ);
    int tid = threadIdx.x;

    float4 a = p[tid];
    float4 b = p[tid + 256];

    float m = fmaxf(fmaxf(fmaxf(a.x, a.y), fmaxf(a.z, a.w)),
                    fmaxf(fmaxf(b.x, b.y), fmaxf(b.z, b.w)));
    m = block_reduce_max(m, sred);

    a.x = __expf(a.x - m); a.y = __expf(a.y - m);
    a.z = __expf(a.z - m); a.w = __expf(a.w - m);
    b.x = __expf(b.x - m); b.y = __expf(b.y - m);
    b.z = __expf(b.z - m); b.w = __expf(b.w - m);

    float s = (a.x + a.y + a.z + a.w) + (b.x + b.y + b.z + b.w);
    __syncthreads();
    s = block_reduce_sum(s, sred);
    float inv = 1.0f / s;

    __nv_bfloat16* outp = reinterpret_cast<__nv_bfloat16*>(P) + row * (size_t)(2 * SEQ);
    uint2 ua, ub;
    ua.x = pack_bf2(a.x * inv, a.y * inv); ua.y = pack_bf2(a.z * inv, a.w * inv);
    ub.x = pack_bf2(b.x * inv, b.y * inv); ub.y = pack_bf2(b.z * inv, b.w * inv);
    *reinterpret_cast<uint2*>(outp + 4 * tid)        = ua;
    *reinterpret_cast<uint2*>(outp + 1024 + 4 * tid) = ub;
}

// ---------------------------------------------------------------------------
// Residual + LayerNorm
// ---------------------------------------------------------------------------
__global__ void __launch_bounds__(256) ln_kernel(
    const float* __restrict__ q, const float* __restrict__ ao,
    const float* __restrict__ gamma, const float* __restrict__ beta,
    float* __restrict__ out)
{
    __shared__ float sred[32];
    size_t row = blockIdx.x;
    int tid = threadIdx.x;

    const float4 qv = reinterpret_cast<const float4*>(q  + row * (size_t)DMODEL)[tid];
    const float4 av = reinterpret_cast<const float4*>(ao + row * (size_t)DMODEL)[tid];
    float x0 = qv.x + av.x, x1 = qv.y + av.y, x2 = qv.z + av.z, x3 = qv.w + av.w;

    float s = x0 + x1 + x2 + x3;
    s = block_reduce_sum(s, sred);
    float mu = s * (1.0f / DMODEL);

    float d0 = x0 - mu, d1 = x1 - mu, d2 = x2 - mu, d3 = x3 - mu;
    float s2 = d0 * d0 + d1 * d1 + d2 * d2 + d3 * d3;
    __syncthreads();
    s2 = block_reduce_sum(s2, sred);
    float rs = rsqrtf(s2 * (1.0f / DMODEL) + 1e-5f);

    const float4 gv = reinterpret_cast<const float4*>(gamma)[tid];
    const float4 bv = reinterpret_cast<const float4*>(beta)[tid];
    float4 o;
    o.x = d0 * rs * gv.x + bv.x;
    o.y = d1 * rs * gv.y + bv.y;
    o.z = d2 * rs * gv.z + bv.z;
    o.w = d3 * rs * gv.w + bv.w;
    reinterpret_cast<float4*>(out + row * (size_t)DMODEL)[tid] = o;
}

// ---------------------------------------------------------------------------
// Launch
// ---------------------------------------------------------------------------
extern "C" void kernel_launch(void* const* d_in, const int* in_sizes, int n_in,
                              void* d_out, int out_size)
{
    const float* q     = (const float*)d_in[0];
    const float* k     = (const float*)d_in[1];
    const float* v     = (const float*)d_in[2];
    const float* Wq    = (const float*)d_in[3];
    const float* Wk    = (const float*)d_in[4];
    const float* bk    = (const float*)d_in[5];
    const float* Wv    = (const float*)d_in[6];
    const float* bv    = (const float*)d_in[7];
    const float* Wo    = (const float*)d_in[8];
    const float* bo    = (const float*)d_in[9];
    const float* gamma = (const float*)d_in[10];
    const float* beta  = (const float*)d_in[11];
    float* out = (float*)d_out;

    __nv_bfloat16 *qb, *kb, *vb, *Wqb, *Wkb, *Wvb, *Wob, *qh, *kh, *vh, *attn;
    float *scores, *attnout;
    cudaGetSymbolAddress((void**)&qb,      g_qb);
    cudaGetSymbolAddress((void**)&kb,      g_kb);
    cudaGetSymbolAddress((void**)&vb,      g_vb);
    cudaGetSymbolAddress((void**)&Wqb,     g_Wqb);
    cudaGetSymbolAddress((void**)&Wkb,     g_Wkb);
    cudaGetSymbolAddress((void**)&Wvb,     g_Wvb);
    cudaGetSymbolAddress((void**)&Wob,     g_Wob);
    cudaGetSymbolAddress((void**)&qh,      g_qh);
    cudaGetSymbolAddress((void**)&kh,      g_kh);
    cudaGetSymbolAddress((void**)&vh,      g_vh);
    cudaGetSymbolAddress((void**)&attn,    g_attn);
    cudaGetSymbolAddress((void**)&scores,  g_scores);
    cudaGetSymbolAddress((void**)&attnout, g_attnout);

    cudaFuncSetAttribute(gemm_qkv,
                         cudaFuncAttributeMaxDynamicSharedMemorySize, SMEM_NT);
    cudaFuncSetAttribute(gemm_bf16<1, float>,
                         cudaFuncAttributeMaxDynamicSharedMemorySize, SMEM_NT);
    cudaFuncSetAttribute(gemm_bf16<0, __nv_bfloat16>,
                         cudaFuncAttributeMaxDynamicSharedMemorySize, SMEM_NN);

    // fused fp32 -> bf16 conversions: q/k/v in one launch, 4 weights in one
    CvtArgs big;
    big.in[0] = q;  big.out[0] = qb;
    big.in[1] = k;  big.out[1] = kb;
    big.in[2] = v;  big.out[2] = vb;
    big.in[3] = q;  big.out[3] = qb;   // unused (z<3)
    f2bf_multi<<<dim3(8192, 1, 3), 256>>>(big, MT_TOK * DMODEL);

    CvtArgs wts;
    wts.in[0] = Wq; wts.out[0] = Wqb;
    wts.in[1] = Wk; wts.out[1] = Wkb;
    wts.in[2] = Wv; wts.out[2] = Wvb;
    wts.in[3] = Wo; wts.out[3] = Wob;
    f2bf_multi<<<dim3(512, 1, 4), 256>>>(wts, DMODEL * DMODEL);

    dim3 blk(256);

    // fused q/k/v projections (NT, bf16 out), one launch, z selects tensor
    QKVArgs pa;
    pa.A[0] = qb;  pa.B[0] = Wqb; pa.C[0] = qh; pa.bias[0] = nullptr; pa.scale[0] = 0.125f;
    pa.A[1] = kb;  pa.B[1] = Wkb; pa.C[1] = kh; pa.bias[1] = bk;      pa.scale[1] = 1.0f;
    pa.A[2] = vb;  pa.B[2] = Wvb; pa.C[2] = vh; pa.bias[2] = bv;      pa.scale[2] = 1.0f;
    gemm_qkv<<<dim3(8, 128, 3), blk, SMEM_NT>>>(pa);

    // scores[b] = qh[b] @ kh[b]^T -> fp32 (direct epilogue)
    gemm_bf16<1, float><<<dim3(16, 16, NBATCH), blk, SMEM_NT>>>(
        qh, kh, scores, SEQ, SEQ, DMODEL, DMODEL, DMODEL,
        (long long)SEQ * DMODEL, (long long)SEQ * DMODEL, (long long)SEQ * SEQ,
        nullptr, 1.0f);

    // softmax -> bf16 probs in place (row stride 4096 bf16)
    softmax_kernel<<<MT_TOK, 256>>>(scores);

    // attn[b] = probs[b] @ vh[b]  (NN, bf16 out)
    gemm_bf16<0, __nv_bfloat16><<<dim3(8, 16, NBATCH), blk, SMEM_NN>>>(
        (const __nv_bfloat16*)scores, vh, attn, SEQ, DMODEL, SEQ,
        2 * SEQ, DMODEL,
        (long long)SEQ * 2 * SEQ, (long long)SEQ * DMODEL, (long long)SEQ * DMODEL,
        nullptr, 1.0f);

    // out-proj (+bo) -> fp32 attn_out
    gemm_bf16<1, float><<<dim3(8, 128, 1), blk, SMEM_NT>>>(
        attn, Wob, attnout, MT_TOK, DMODEL, DMODEL, DMODEL, DMODEL,
        0, 0, 0, bo, 1.0f);

    // residual + LN
    ln_kernel<<<MT_TOK, 256>>>(q, attnout, gamma, beta, out);
}

// round 17
// speedup vs baseline: 1.0150x; 1.0150x over previous
#include <cuda_runtime.h>
#include <cuda_bf16.h>
#include <mma.h>
#include <type_traits>
#include <cstdint>

using namespace nvcuda;

#define MT_TOK 16384
#define DMODEL 1024
#define SEQ    2048
#define NBATCH 8

// ---------------------------------------------------------------------------
// Scratch (device globals; allocation-free rule)
// ---------------------------------------------------------------------------
__device__ __nv_bfloat16 g_qb [MT_TOK * DMODEL];
__device__ __nv_bfloat16 g_kb [MT_TOK * DMODEL];
__device__ __nv_bfloat16 g_vb [MT_TOK * DMODEL];
__device__ __nv_bfloat16 g_Wqb[DMODEL * DMODEL];
__device__ __nv_bfloat16 g_Wkb[DMODEL * DMODEL];
__device__ __nv_bfloat16 g_Wvb[DMODEL * DMODEL];
__device__ __nv_bfloat16 g_Wob[DMODEL * DMODEL];
__device__ __nv_bfloat16 g_qh [MT_TOK * DMODEL];   // q-proj out (pre-scaled)
__device__ __nv_bfloat16 g_kh [MT_TOK * DMODEL];   // k-proj out (+bk)
__device__ __nv_bfloat16 g_vh [MT_TOK * DMODEL];   // v-proj out (+bv)
__device__ __nv_bfloat16 g_attn[MT_TOK * DMODEL];  // P@V out
__device__ float         g_scores[(size_t)NBATCH * SEQ * SEQ]; // fp32 scores; bf16 probs in place
__device__ float         g_attnout[MT_TOK * DMODEL];

__device__ __forceinline__ uint32_t pack_bf2(float a, float b)
{
    __nv_bfloat162 h = __floats2bfloat162_rn(a, b);
    return *reinterpret_cast<uint32_t*>(&h);
}

// ---------------------------------------------------------------------------
// cp.async helpers
// ---------------------------------------------------------------------------
__device__ __forceinline__ void cp_async16(void* smem_ptr, const void* gmem_ptr)
{
    unsigned s = (unsigned)__cvta_generic_to_shared(smem_ptr);
    asm volatile("cp.async.cg.shared.global [%0], [%1], 16;\n" :: "r"(s), "l"(gmem_ptr));
}
__device__ __forceinline__ void cp_commit()
{
    asm volatile("cp.async.commit_group;\n" ::: "memory");
}
template <int N>
__device__ __forceinline__ void cp_wait()
{
    asm volatile("cp.async.wait_group %0;\n" :: "n"(N) : "memory");
}

// ---------------------------------------------------------------------------
// bf16 WMMA GEMM (m16n16k16, fp32 accum), 2-stage cp.async pipeline:
//   C[M,N] = scale * (A[M,K] @ op(B)) + bias[N]
//   BT=1: B is [N,K] row-major (NT)    BT=0: B is [K,N] row-major (NN)
//   OutT: float or __nv_bfloat16.
// Block tile 128x128x32, 8 warps (warp tile 64x32). M%128==N%128==0, K%32==0.
// 2 CTAs/SM (this is the measured-optimal configuration: the legacy HMMA
// pipe saturates at ~250 TF/s with this concurrency; deeper pipelines,
// denser tiles, and load reordering all measured neutral-or-worse).
// ---------------------------------------------------------------------------
template <int BT, typename OutT>
__global__ void __launch_bounds__(256, 2) gemm_bf16(
    const __nv_bfloat16* __restrict__ A, const __nv_bfloat16* __restrict__ Bm,
    OutT* __restrict__ C, int M, int N, int K, int lda, int ldb,
    long long sA, long long sB, long long sC,
    const float* __restrict__ bias, float scale)
{
    constexpr int LDA = 40;                  // 32 + 8 pad, 80B rows (16B mult)
    constexpr int LDB = BT ? 40 : 136;       // NN: 272B rows (16B mult)
    constexpr int BSZ = BT ? (128 * 40) : (32 * 136);

    __shared__ __align__(16) __nv_bfloat16 As[2][128 * 40];
    __shared__ __align__(16) __nv_bfloat16 Bs[2][BSZ];

    const int tid  = threadIdx.x;
    const int warp = tid >> 5;
    const int lane = tid & 31;
    const int wm   = warp & 1;   // 2 warps over M (64 rows)
    const int wn   = warp >> 1;  // 4 warps over N (32 cols)

    const long long bz = blockIdx.z;
    A  += bz * sA;
    Bm += bz * sB;
    C  += bz * sC;

    const int tm = blockIdx.y * 128;
    const int tn = blockIdx.x * 128;

    // A loads: 512 x 16B chunks (2/thread). row = idx>>2, c8 = (idx&3)*8
    const int ar  = tid >> 2;
    const int ac8 = (tid & 3) * 8;
    // B loads
    const int br  = BT ? ar : (tid >> 4);
    const int bc8 = BT ? ac8 : ((tid & 15) * 8);

    const __nv_bfloat16* Aor = A + (size_t)(tm + ar) * lda + ac8;
    const __nv_bfloat16* Bor = BT ? (Bm + (size_t)(tn + br) * ldb + bc8)
                                  : (Bm + (size_t)br * ldb + tn + bc8);

    auto load_stage = [&](int buf, int k0) {
#pragma unroll
        for (int it = 0; it < 2; it++)
            cp_async16(&As[buf][(ar + it * 64) * LDA + ac8],
                       Aor + (size_t)(it * 64) * lda + k0);
        if (BT) {
#pragma unroll
            for (int it = 0; it < 2; it++)
                cp_async16(&Bs[buf][(br + it * 64) * LDB + bc8],
                           Bor + (size_t)(it * 64) * ldb + k0);
        } else {
#pragma unroll
            for (int it = 0; it < 2; it++)
                cp_async16(&Bs[buf][(br + it * 16) * LDB + bc8],
                           Bor + (size_t)(k0 + it * 16) * ldb);
        }
        cp_commit();
    };

    using BLayout = typename std::conditional<(BT != 0), wmma::col_major, wmma::row_major>::type;

    wmma::fragment<wmma::accumulator, 16, 16, 16, float> fc[4][2];
#pragma unroll
    for (int i = 0; i < 4; i++)
#pragma unroll
        for (int j = 0; j < 2; j++) wmma::fill_fragment(fc[i][j], 0.0f);

    const int nk = K >> 5;
    load_stage(0, 0);

    for (int kt = 0; kt < nk; kt++) {
        if (kt + 1 < nk) load_stage((kt + 1) & 1, (kt + 1) << 5);
        if (kt + 1 < nk) cp_wait<1>(); else cp_wait<0>();
        __syncthreads();

        const __nv_bfloat16* as = As[kt & 1];
        const __nv_bfloat16* bs = Bs[kt & 1];
#pragma unroll
        for (int kk = 0; kk < 32; kk += 16) {
            wmma::fragment<wmma::matrix_a, 16, 16, 16, __nv_bfloat16, wmma::row_major> fa[4];
            wmma::fragment<wmma::matrix_b, 16, 16, 16, __nv_bfloat16, BLayout> fb[2];
#pragma unroll
            for (int i = 0; i < 4; i++)
                wmma::load_matrix_sync(fa[i], &as[(wm * 64 + i * 16) * LDA + kk], LDA);
#pragma unroll
            for (int j = 0; j < 2; j++) {
                if (BT)
                    wmma::load_matrix_sync(fb[j], &bs[(wn * 32 + j * 16) * LDB + kk], LDB);
                else
                    wmma::load_matrix_sync(fb[j], &bs[kk * LDB + wn * 32 + j * 16], LDB);
            }
#pragma unroll
            for (int i = 0; i < 4; i++)
#pragma unroll
                for (int j = 0; j < 2; j++)
                    wmma::mma_sync(fc[i][j], fa[i], fb[j], fc[i][j]);
        }
        __syncthreads();
    }

    // ---- epilogue ----
    constexpr bool OUT_F32 = std::is_same<OutT, float>::value;
    if (OUT_F32 && bias == nullptr) {
        // direct fragment -> global fp32
#pragma unroll
        for (int i = 0; i < 4; i++)
#pragma unroll
            for (int j = 0; j < 2; j++) {
#pragma unroll
                for (int t = 0; t < fc[i][j].num_elements; t++) fc[i][j].x[t] *= scale;
                int gr = tm + wm * 64 + i * 16;
                int gc = tn + wn * 32 + j * 16;
                wmma::store_matrix_sync((float*)C + (size_t)gr * N + gc, fc[i][j], N,
                                        wmma::mem_row_major);
            }
    } else {
        // bounce via smem (reuse As; dead after mainloop's final __syncthreads)
        float* ct = reinterpret_cast<float*>(&As[0][0]) + warp * 256;
#pragma unroll
        for (int i = 0; i < 4; i++) {
#pragma unroll
            for (int j = 0; j < 2; j++) {
#pragma unroll
                for (int t = 0; t < fc[i][j].num_elements; t++) fc[i][j].x[t] *= scale;
                wmma::store_matrix_sync(ct, fc[i][j], 16, wmma::mem_row_major);
                __syncwarp();
                int r  = lane >> 1;
                int cb = (lane & 1) * 8;
                int gr = tm + wm * 64 + i * 16 + r;
                int gc = tn + wn * 32 + j * 16 + cb;
                float v[8];
#pragma unroll
                for (int e = 0; e < 8; e++) {
                    v[e] = ct[r * 16 + cb + e];
                    if (bias) v[e] += __ldg(&bias[gc + e]);
                }
                if (OUT_F32) {
                    float* cp = (float*)C + (size_t)gr * N + gc;
                    *reinterpret_cast<float4*>(cp)     = make_float4(v[0], v[1], v[2], v[3]);
                    *reinterpret_cast<float4*>(cp + 4) = make_float4(v[4], v[5], v[6], v[7]);
                } else {
                    __nv_bfloat16* cp = (__nv_bfloat16*)C + (size_t)gr * N + gc;
                    uint4 u;
                    u.x = pack_bf2(v[0], v[1]); u.y = pack_bf2(v[2], v[3]);
                    u.z = pack_bf2(v[4], v[5]); u.w = pack_bf2(v[6], v[7]);
                    *reinterpret_cast<uint4*>(cp) = u;
                }
                __syncwarp();
            }
        }
    }
}

// ---------------------------------------------------------------------------
// fp32 -> bf16 conversion (8 elems/thread)
// ---------------------------------------------------------------------------
__global__ void __launch_bounds__(256) f2bf_kernel(const float* __restrict__ in,
                                                   __nv_bfloat16* __restrict__ out, int n)
{
    int i = (blockIdx.x * 256 + threadIdx.x) * 8;
    if (i >= n) return;
    float4 a = *reinterpret_cast<const float4*>(in + i);
    float4 b = *reinterpret_cast<const float4*>(in + i + 4);
    uint4 u;
    u.x = pack_bf2(a.x, a.y); u.y = pack_bf2(a.z, a.w);
    u.z = pack_bf2(b.x, b.y); u.w = pack_bf2(b.z, b.w);
    *reinterpret_cast<uint4*>(out + i) = u;
}

// ---------------------------------------------------------------------------
// reductions
// ---------------------------------------------------------------------------
__device__ __forceinline__ float block_reduce_max(float v, float* sred)
{
    int lane = threadIdx.x & 31, warp = threadIdx.x >> 5;
#pragma unroll
    for (int o = 16; o > 0; o >>= 1) v = fmaxf(v, __shfl_xor_sync(0xffffffffu, v, o));
    if (lane == 0) sred[warp] = v;
    __syncthreads();
    if (warp == 0) {
        v = (lane < 8) ? sred[lane] : -3.402823e38f;
#pragma unroll
        for (int o = 4; o > 0; o >>= 1) v = fmaxf(v, __shfl_xor_sync(0xffffffffu, v, o));
        if (lane == 0) sred[0] = v;
    }
    __syncthreads();
    return sred[0];
}
__device__ __forceinline__ float block_reduce_sum(float v, float* sred)
{
    int lane = threadIdx.x & 31, warp = threadIdx.x >> 5;
#pragma unroll
    for (int o = 16; o > 0; o >>= 1) v += __shfl_xor_sync(0xffffffffu, v, o);
    if (lane == 0) sred[warp] = v;
    __syncthreads();
    if (warp == 0) {
        v = (lane < 8) ? sred[lane] : 0.0f;
#pragma unroll
        for (int o = 4; o > 0; o >>= 1) v += __shfl_xor_sync(0xffffffffu, v, o);
        if (lane == 0) sred[0] = v;
    }
    __syncthreads();
    return sred[0];
}

// ---------------------------------------------------------------------------
// Softmax over 2048 fp32 -> bf16 probs in place (row stride preserved)
// ---------------------------------------------------------------------------
__global__ void __launch_bounds__(256) softmax_kernel(float* __restrict__ P)
{
    __shared__ float sred[32];
    size_t row = blockIdx.x;
    float4* p = reinterpret_cast<float4*>(P + row * (size_t)SEQ);
    int tid = threadIdx.x;

    float4 a = p[tid];
    float4 b = p[tid + 256];

    float m = fmaxf(fmaxf(fmaxf(a.x, a.y), fmaxf(a.z, a.w)),
                    fmaxf(fmaxf(b.x, b.y), fmaxf(b.z, b.w)));
    m = block_reduce_max(m, sred);

    a.x = __expf(a.x - m); a.y = __expf(a.y - m);
    a.z = __expf(a.z - m); a.w = __expf(a.w - m);
    b.x = __expf(b.x - m); b.y = __expf(b.y - m);
    b.z = __expf(b.z - m); b.w = __expf(b.w - m);

    float s = (a.x + a.y + a.z + a.w) + (b.x + b.y + b.z + b.w);
    __syncthreads();
    s = block_reduce_sum(s, sred);
    float inv = 1.0f / s;

    __nv_bfloat16* outp = reinterpret_cast<__nv_bfloat16*>(P) + row * (size_t)(2 * SEQ);
    uint2 ua, ub;
    ua.x = pack_bf2(a.x * inv, a.y * inv); ua.y = pack_bf2(a.z * inv, a.w * inv);
    ub.x = pack_bf2(b.x * inv, b.y * inv); ub.y = pack_bf2(b.z * inv, b.w * inv);
    *reinterpret_cast<uint2*>(outp + 4 * tid)        = ua;
    *reinterpret_cast<uint2*>(outp + 1024 + 4 * tid) = ub;
}

// ---------------------------------------------------------------------------
// Residual + LayerNorm
// ---------------------------------------------------------------------------
__global__ void __launch_bounds__(256) ln_kernel(
    const float* __restrict__ q, const float* __restrict__ ao,
    const float* __restrict__ gamma, const float* __restrict__ beta,
    float* __restrict__ out)
{
    __shared__ float sred[32];
    size_t row = blockIdx.x;
    int tid = threadIdx.x;

    const float4 qv = reinterpret_cast<const float4*>(q  + row * (size_t)DMODEL)[tid];
    const float4 av = reinterpret_cast<const float4*>(ao + row * (size_t)DMODEL)[tid];
    float x0 = qv.x + av.x, x1 = qv.y + av.y, x2 = qv.z + av.z, x3 = qv.w + av.w;

    float s = x0 + x1 + x2 + x3;
    s = block_reduce_sum(s, sred);
    float mu = s * (1.0f / DMODEL);

    float d0 = x0 - mu, d1 = x1 - mu, d2 = x2 - mu, d3 = x3 - mu;
    float s2 = d0 * d0 + d1 * d1 + d2 * d2 + d3 * d3;
    __syncthreads();
    s2 = block_reduce_sum(s2, sred);
    float rs = rsqrtf(s2 * (1.0f / DMODEL) + 1e-5f);

    const float4 gv = reinterpret_cast<const float4*>(gamma)[tid];
    const float4 bv = reinterpret_cast<const float4*>(beta)[tid];
    float4 o;
    o.x = d0 * rs * gv.x + bv.x;
    o.y = d1 * rs * gv.y + bv.y;
    o.z = d2 * rs * gv.z + bv.z;
    o.w = d3 * rs * gv.w + bv.w;
    reinterpret_cast<float4*>(out + row * (size_t)DMODEL)[tid] = o;
}

// ---------------------------------------------------------------------------
// Launch
// ---------------------------------------------------------------------------
extern "C" void kernel_launch(void* const* d_in, const int* in_sizes, int n_in,
                              void* d_out, int out_size)
{
    const float* q     = (const float*)d_in[0];
    const float* k     = (const float*)d_in[1];
    const float* v     = (const float*)d_in[2];
    const float* Wq    = (const float*)d_in[3];
    const float* Wk    = (const float*)d_in[4];
    const float* bk    = (const float*)d_in[5];
    const float* Wv    = (const float*)d_in[6];
    const float* bv    = (const float*)d_in[7];
    const float* Wo    = (const float*)d_in[8];
    const float* bo    = (const float*)d_in[9];
    const float* gamma = (const float*)d_in[10];
    const float* beta  = (const float*)d_in[11];
    float* out = (float*)d_out;

    __nv_bfloat16 *qb, *kb, *vb, *Wqb, *Wkb, *Wvb, *Wob, *qh, *kh, *vh, *attn;
    float *scores, *attnout;
    cudaGetSymbolAddress((void**)&qb,      g_qb);
    cudaGetSymbolAddress((void**)&kb,      g_kb);
    cudaGetSymbolAddress((void**)&vb,      g_vb);
    cudaGetSymbolAddress((void**)&Wqb,     g_Wqb);
    cudaGetSymbolAddress((void**)&Wkb,     g_Wkb);
    cudaGetSymbolAddress((void**)&Wvb,     g_Wvb);
    cudaGetSymbolAddress((void**)&Wob,     g_Wob);
    cudaGetSymbolAddress((void**)&qh,      g_qh);
    cudaGetSymbolAddress((void**)&kh,      g_kh);
    cudaGetSymbolAddress((void**)&vh,      g_vh);
    cudaGetSymbolAddress((void**)&attn,    g_attn);
    cudaGetSymbolAddress((void**)&scores,  g_scores);
    cudaGetSymbolAddress((void**)&attnout, g_attnout);

    // fp32 -> bf16 conversions
    f2bf_kernel<<<8192, 256>>>(q,  qb, MT_TOK * DMODEL);
    f2bf_kernel<<<8192, 256>>>(k,  kb, MT_TOK * DMODEL);
    f2bf_kernel<<<8192, 256>>>(v,  vb, MT_TOK * DMODEL);
    f2bf_kernel<<<512,  256>>>(Wq, Wqb, DMODEL * DMODEL);
    f2bf_kernel<<<512,  256>>>(Wk, Wkb, DMODEL * DMODEL);
    f2bf_kernel<<<512,  256>>>(Wv, Wvb, DMODEL * DMODEL);
    f2bf_kernel<<<512,  256>>>(Wo, Wob, DMODEL * DMODEL);

    dim3 blk(256);

    // projections (NT, bf16 out): [16384,1024] @ [1024,1024]^T
    gemm_bf16<1, __nv_bfloat16><<<dim3(8, 128, 1), blk>>>(
        qb, Wqb, qh, MT_TOK, DMODEL, DMODEL, DMODEL, DMODEL,
        0, 0, 0, nullptr, 0.125f);
    gemm_bf16<1, __nv_bfloat16><<<dim3(8, 128, 1), blk>>>(
        kb, Wkb, kh, MT_TOK, DMODEL, DMODEL, DMODEL, DMODEL,
        0, 0, 0, bk, 1.0f);
    gemm_bf16<1, __nv_bfloat16><<<dim3(8, 128, 1), blk>>>(
        vb, Wvb, vh, MT_TOK, DMODEL, DMODEL, DMODEL, DMODEL,
        0, 0, 0, bv, 1.0f);

    // scores[b] = qh[b] @ kh[b]^T -> fp32 (direct epilogue)
    gemm_bf16<1, float><<<dim3(16, 16, NBATCH), blk>>>(
        qh, kh, scores, SEQ, SEQ, DMODEL, DMODEL, DMODEL,
        (long long)SEQ * DMODEL, (long long)SEQ * DMODEL, (long long)SEQ * SEQ,
        nullptr, 1.0f);

    // softmax -> bf16 probs in place (row stride 4096 bf16)
    softmax_kernel<<<MT_TOK, 256>>>(scores);

    // attn[b] = probs[b] @ vh[b]  (NN, bf16 out)
    gemm_bf16<0, __nv_bfloat16><<<dim3(8, 16, NBATCH), blk>>>(
        (const __nv_bfloat16*)scores, vh, attn, SEQ, DMODEL, SEQ,
        2 * SEQ, DMODEL,
        (long long)SEQ * 2 * SEQ, (long long)SEQ * DMODEL, (long long)SEQ * DMODEL,
        nullptr, 1.0f);

    // out-proj (+bo) -> fp32 attn_out
    gemm_bf16<1, float><<<dim3(8, 128, 1), blk>>>(
        attn, Wob, attnout, MT_TOK, DMODEL, DMODEL, DMODEL, DMODEL,
        0, 0, 0, bo, 1.0f);

    // residual + LN
    ln_kernel<<<MT_TOK, 256>>>(q, attnout, gamma, beta, out);
}